// round 12
// baseline (speedup 1.0000x reference)
#include <cuda_runtime.h>
#include <cuda.h>
#include <cstdint>

// ============================================================================
// DenseBlockEnd: out = relu(mask * (node + beta1*einsum(ib,W_in) + beta2*einsum(bo,W_out)))
// Fused GEMM M=131072, N=256, K=768 via warp-level mma.sync tf32.
// CTA = 128 rows x 256 cols. 16 compute warps (32x64 each) + 1 TMA producer.
// R11: revert R10 double-buffer (it spilled: L2/fma/alu signature). Add
// masked-row work skipping at warp (32-row) and mt (16-row) granularity:
// ~25% of LDSM+HMMA eliminated on average.
// ============================================================================

#define FDIM    256
#define KTOT    768
#define CTA_M   128
#define KC      32
#define NCHUNK  (KTOT / KC)         // 24
#define STAGES  4
#define A_STAGE (CTA_M * KC * 4)    // 16384
#define B_STAGE (FDIM * KC * 4)     // 32768
#define STAGE_BYTES (A_STAGE + B_STAGE)   // 49152
#define SMEM_HDR    1024
#define SMEM_TOTAL  (SMEM_HDR + STAGES * STAGE_BYTES)  // 197632
#define NCWARP      16
#define NTHREADS    (NCWARP * 32 + 32)    // 544

// Weight scratch: Wt[n][k] = beta(seg) * W_seg[k%256][n], tf32-RNA-rounded.
__device__ __align__(1024) float g_Wt[FDIM * KTOT];

// ---------------------------------------------------------------------------
// PTX helpers
// ---------------------------------------------------------------------------
__device__ __forceinline__ uint32_t smem_u32(const void* p) {
    uint32_t a;
    asm("{ .reg .u64 t; cvta.to.shared.u64 t, %1; cvt.u32.u64 %0, t; }" : "=r"(a) : "l"(p));
    return a;
}

#define MBAR_INIT(addr, cnt) \
    asm volatile("mbarrier.init.shared.b64 [%0], %1;" :: "r"(addr), "r"(cnt) : "memory")

#define MBAR_EXPECT(addr, bytes) \
    asm volatile("mbarrier.arrive.expect_tx.shared.b64 _, [%0], %1;" \
                 :: "r"(addr), "r"((uint32_t)(bytes)) : "memory")

#define MBAR_ARRIVE(addr) \
    asm volatile("mbarrier.arrive.shared.b64 _, [%0];" :: "r"(addr) : "memory")

#define MBAR_WAIT(addr, par) do { \
    asm volatile("{\n\t.reg .pred P;\n\tWL_%=:\n\t" \
        "mbarrier.try_wait.parity.acquire.cta.shared::cta.b64 P, [%0], %1, 0x989680;\n\t" \
        "@P bra.uni WD_%=;\n\tbra.uni WL_%=;\n\tWD_%=:\n\t}" \
        :: "r"(addr), "r"((uint32_t)(par)) : "memory"); \
} while (0)

__device__ __forceinline__ void tma2d(uint32_t dst, const void* map, int x, int y, uint32_t mbar) {
    asm volatile(
        "cp.async.bulk.tensor.2d.shared::cta.global.tile.mbarrier::complete_tx::bytes "
        "[%0], [%1, {%2, %3}], [%4];"
        :: "r"(dst), "l"(map), "r"(x), "r"(y), "r"(mbar) : "memory");
}

__device__ __forceinline__ uint32_t swz(uint32_t b) {   // SW128: bits[6:4] ^= bits[9:7]
    return b ^ ((b >> 3) & 0x70);
}

// ldmatrix x4: four 8x8 b16 submatrices (= four 8x4 tf32 tiles).
__device__ __forceinline__ void ldsm_x4(uint32_t* r, uint32_t addr) {
    asm volatile("ldmatrix.sync.aligned.m8n8.x4.shared.b16 {%0,%1,%2,%3}, [%4];"
        : "=r"(r[0]), "=r"(r[1]), "=r"(r[2]), "=r"(r[3]) : "r"(addr));
}

// D += A(16x8, row) * B(8x8, col); tf32 operands in raw b32 regs, fp32 accum.
__device__ __forceinline__ void mma_tf32(float* d, const uint32_t* a, const uint32_t* b) {
    asm volatile(
        "mma.sync.aligned.m16n8k8.row.col.f32.tf32.tf32.f32 "
        "{%0,%1,%2,%3}, {%4,%5,%6,%7}, {%8,%9}, {%0,%1,%2,%3};"
        : "+f"(d[0]), "+f"(d[1]), "+f"(d[2]), "+f"(d[3])
        : "r"(a[0]), "r"(a[1]), "r"(a[2]), "r"(a[3]), "r"(b[0]), "r"(b[1]));
}

// ---------------------------------------------------------------------------
// Prologue: scaled, transposed, tf32-RNA-rounded weights -> g_Wt[n][k]
// ---------------------------------------------------------------------------
__global__ void prep_weights(const float* __restrict__ W_in, const float* __restrict__ W_out,
                             const float* __restrict__ beta1, const float* __restrict__ beta2) {
    int idx = blockIdx.x * blockDim.x + threadIdx.x;
    if (idx >= FDIM * KTOT) return;
    int n = idx / KTOT;
    int k = idx - n * KTOT;
    int seg = k >> 8;           // 0,1 -> W_in layer; 2 -> W_out
    int kk  = k & 255;
    float v;
    if (seg < 2) v = beta1[0] * W_in[seg * 65536 + kk * 256 + n];
    else         v = beta2[0] * W_out[kk * 256 + n];
    uint32_t u;
    asm("cvt.rna.tf32.f32 %0, %1;" : "=r"(u) : "f"(v));
    g_Wt[idx] = __uint_as_float(u);
}

// ---------------------------------------------------------------------------
// Main kernel
// ---------------------------------------------------------------------------
__global__ void __launch_bounds__(NTHREADS, 1) dense_block_end(
    const __grid_constant__ CUtensorMap tma_ib,   // inblock_acts viewed [262144, 256] f32
    const __grid_constant__ CUtensorMap tma_bo,   // block_outputs viewed [131072, 256] f32
    const __grid_constant__ CUtensorMap tma_w,    // g_Wt viewed [256 n, 768 k] f32
    const float* __restrict__ node,
    const int*   __restrict__ mol_slice,
    float*       __restrict__ out)
{
    extern __shared__ char smem[];
    const uint32_t sb  = smem_u32(smem);
    const int tid = threadIdx.x;
    const int wid = tid >> 5;
    const int lid = tid & 31;
    const int bid = blockIdx.x;
    const int R0  = bid * CTA_M;                 // global row base

    const int slice     = mol_slice[bid >> 1];
    const int slice_loc = slice - ((bid & 1) << 7);    // rows valid in this CTA

    // ---- fully-masked CTA: zero-fill 128x256 and exit (no loads, no MMA) ----
    if (slice_loc <= 0) {
        float4* o4 = (float4*)(out + (size_t)R0 * FDIM);
        const float4 z = make_float4(0.f, 0.f, 0.f, 0.f);
        for (int i = tid; i < CTA_M * (FDIM / 4); i += NTHREADS) o4[i] = z;
        return;
    }

    // barriers: full[s] @ sb + 8s (s=0..3), empty[s] @ sb + 32 + 8s
    if (tid == 0) {
        #pragma unroll
        for (int s = 0; s < STAGES; ++s) {
            MBAR_INIT(sb + 8 * s, 1);            // full: 1 expect-tx arrival
            MBAR_INIT(sb + 32 + 8 * s, NCWARP);  // empty: all compute warps
        }
    }
    __syncthreads();

    // ------------------------- producer warp (wid == 16) --------------------
    if (wid == NCWARP) {
        if (lid == 0) {
            #pragma unroll 1
            for (int c = 0; c < NCHUNK; ++c) {
                const int s  = c & 3;
                const int pe = 1 ^ ((c >> 2) & 1);     // flipped phase: first pass free
                MBAR_WAIT(sb + 32 + 8 * s, pe);
                const uint32_t mb = sb + 8 * s;
                MBAR_EXPECT(mb, STAGE_BYTES);
                const int seg = c >> 3;                 // 8 chunks per 256-K segment
                const int k0  = (c & 7) * KC;
                const int y   = (seg == 1) ? 131072 + R0 : R0;
                const void* mp = (seg < 2) ? (const void*)&tma_ib : (const void*)&tma_bo;
                const uint32_t stg = sb + SMEM_HDR + s * STAGE_BYTES;
                tma2d(stg,           mp,     k0,     y, mb);   // A: 128 rows x 32 k
                tma2d(stg + A_STAGE, &tma_w, c * KC, 0, mb);   // B: 256 n   x 32 k
            }
        }
        return;
    }

    // ------------------------- compute warps (wid 0..15) --------------------
    const int wm   = wid >> 2;         // warp row (0..3) -> 32 rows
    const int wn   = wid & 3;          // warp col (0..3) -> 64 cols
    const int sub  = lid >> 3;         // ldmatrix submatrix id (0..3)
    const int srow = lid & 7;          // row within submatrix

    // ldmatrix lane-address row/k decomposition (see R9):
    const uint32_t aRowL = (uint32_t)(wm * 32 + (sub & 1) * 8 + srow);
    const uint32_t aKoff = (uint32_t)((sub >> 1) * 4);
    const uint32_t bRowL = (uint32_t)(wn * 64 + (sub >> 1) * 8 + srow);
    const uint32_t bKoff = (uint32_t)((sub & 1) * 4);

    const int warp_rows = slice_loc - wm * 32;   // >0: this warp has live rows
    float acc[2][8][4];                          // 64 accumulator regs
    #pragma unroll
    for (int i = 0; i < 2; ++i)
        #pragma unroll
        for (int j = 0; j < 8; ++j)
            #pragma unroll
            for (int q = 0; q < 4; ++q) acc[i][j][q] = 0.f;

    if (warp_rows <= 0) {
        // fully-masked warp: keep barrier protocol alive, do no LDSM/MMA work
        #pragma unroll 1
        for (int c = 0; c < NCHUNK; ++c) {
            const int s = c & 3;
            MBAR_WAIT(sb + 8 * s, (c >> 2) & 1);
            __syncwarp();
            if (lid == 0) MBAR_ARRIVE(sb + 32 + 8 * s);
        }
    } else {
        const bool do_mt1 = (warp_rows > 16);    // upper 16 rows of this warp live?
        #pragma unroll 1
        for (int c = 0; c < NCHUNK; ++c) {
            const int s = c & 3;
            MBAR_WAIT(sb + 8 * s, (c >> 2) & 1);
            const uint32_t aBase = sb + SMEM_HDR + s * STAGE_BYTES;
            const uint32_t bBase = aBase + A_STAGE;

            #pragma unroll
            for (int ks = 0; ks < 4; ++ks) {
                const uint32_t k0 = ks * 8;
                uint32_t af[2][4];
                ldsm_x4(af[0], aBase + swz(aRowL * 128 + (k0 + aKoff) * 4));
                if (do_mt1)
                    ldsm_x4(af[1], aBase + swz((aRowL + 16) * 128 + (k0 + aKoff) * 4));
                uint32_t bf[4][4];
                #pragma unroll
                for (int pr = 0; pr < 4; ++pr)   // pr covers nt pair (2*pr, 2*pr+1)
                    ldsm_x4(bf[pr], bBase + swz((bRowL + pr * 16) * 128 + (k0 + bKoff) * 4));
                #pragma unroll
                for (int nt = 0; nt < 8; ++nt)
                    mma_tf32(acc[0][nt], af[0], &bf[nt >> 1][(nt & 1) * 2]);
                if (do_mt1) {
                    #pragma unroll
                    for (int nt = 0; nt < 8; ++nt)
                        mma_tf32(acc[1][nt], af[1], &bf[nt >> 1][(nt & 1) * 2]);
                }
            }
            __syncwarp();
            if (lid == 0) MBAR_ARRIVE(sb + 32 + 8 * s);   // stage reusable
        }
    }

    // ------------------------- fused epilogue -------------------------------
    // D frag: c0:(g,2tig) c1:(g,2tig+1) c2:(g+8,2tig) c3:(g+8,2tig+1)
    const int g   = lid >> 2;
    const int tig = lid & 3;
    #pragma unroll
    for (int mt = 0; mt < 2; ++mt) {
        #pragma unroll
        for (int h = 0; h < 2; ++h) {
            const int rloc = wm * 32 + mt * 16 + g + h * 8;
            float2* orow = (float2*)(out + (size_t)(R0 + rloc) * FDIM);
            if (rloc < slice_loc) {
                const float2* nrow = (const float2*)(node + (size_t)(R0 + rloc) * FDIM);
                #pragma unroll
                for (int nt = 0; nt < 8; ++nt) {
                    const int ci = (wn * 64 + nt * 8 + 2 * tig) >> 1;   // float2 index
                    const float2 nv = nrow[ci];
                    float2 o;
                    o.x = fmaxf(nv.x + acc[mt][nt][h * 2 + 0], 0.f);
                    o.y = fmaxf(nv.y + acc[mt][nt][h * 2 + 1], 0.f);
                    orow[ci] = o;
                }
            } else {
                const float2 z = make_float2(0.f, 0.f);
                #pragma unroll
                for (int nt = 0; nt < 8; ++nt)
                    orow[(wn * 64 + nt * 8 + 2 * tig) >> 1] = z;
            }
        }
    }
}

// ---------------------------------------------------------------------------
// Host launcher
// ---------------------------------------------------------------------------
typedef CUresult (CUDAAPI *PFN_TMAP)(
    CUtensorMap*, CUtensorMapDataType, cuuint32_t, void*,
    const cuuint64_t*, const cuuint64_t*, const cuuint32_t*, const cuuint32_t*,
    CUtensorMapInterleave, CUtensorMapSwizzle, CUtensorMapL2promotion, CUtensorMapFloatOOBfill);

extern "C" void kernel_launch(void* const* d_in, const int* in_sizes, int n_in,
                              void* d_out, int out_size) {
    const float* node  = (const float*)d_in[0];
    const float* ib    = (const float*)d_in[1];
    const float* bo    = (const float*)d_in[2];
    const int*   msl   = (const int*)d_in[3];
    const float* W_in  = (const float*)d_in[4];
    const float* W_out = (const float*)d_in[5];
    const float* b1    = (const float*)d_in[6];
    const float* b2    = (const float*)d_in[7];
    float* out = (float*)d_out;

    static PFN_TMAP pfn = nullptr;
    if (!pfn) {
        void* p = nullptr;
        cudaDriverEntryPointQueryResult qr;
        cudaGetDriverEntryPoint("cuTensorMapEncodeTiled", &p, cudaEnableDefault, &qr);
        pfn = (PFN_TMAP)p;
    }
    void* wptr = nullptr;
    cudaGetSymbolAddress(&wptr, g_Wt);

    CUtensorMap m_ib, m_bo, m_w;
    {   // inblock_acts as [2*131072 rows, 256 floats]; box = 32 x 128
        cuuint64_t dims[2]    = {256, 2ull * 131072};
        cuuint64_t strides[1] = {256 * 4};
        cuuint32_t box[2]     = {KC, CTA_M};
        cuuint32_t es[2]      = {1, 1};
        pfn(&m_ib, CU_TENSOR_MAP_DATA_TYPE_FLOAT32, 2, (void*)ib, dims, strides, box, es,
            CU_TENSOR_MAP_INTERLEAVE_NONE, CU_TENSOR_MAP_SWIZZLE_128B,
            CU_TENSOR_MAP_L2_PROMOTION_L2_128B, CU_TENSOR_MAP_FLOAT_OOB_FILL_NONE);
    }
    {   // block_outputs as [131072 rows, 256 floats]; box = 32 x 128
        cuuint64_t dims[2]    = {256, 131072};
        cuuint64_t strides[1] = {256 * 4};
        cuuint32_t box[2]     = {KC, CTA_M};
        cuuint32_t es[2]      = {1, 1};
        pfn(&m_bo, CU_TENSOR_MAP_DATA_TYPE_FLOAT32, 2, (void*)bo, dims, strides, box, es,
            CU_TENSOR_MAP_INTERLEAVE_NONE, CU_TENSOR_MAP_SWIZZLE_128B,
            CU_TENSOR_MAP_L2_PROMOTION_L2_128B, CU_TENSOR_MAP_FLOAT_OOB_FILL_NONE);
    }
    {   // weights scratch [256 rows(n), 768 floats(k)]; box = 32 x 256
        cuuint64_t dims[2]    = {KTOT, 256};
        cuuint64_t strides[1] = {KTOT * 4};
        cuuint32_t box[2]     = {KC, 256};
        cuuint32_t es[2]      = {1, 1};
        pfn(&m_w, CU_TENSOR_MAP_DATA_TYPE_FLOAT32, 2, wptr, dims, strides, box, es,
            CU_TENSOR_MAP_INTERLEAVE_NONE, CU_TENSOR_MAP_SWIZZLE_128B,
            CU_TENSOR_MAP_L2_PROMOTION_L2_128B, CU_TENSOR_MAP_FLOAT_OOB_FILL_NONE);
    }

    prep_weights<<<(FDIM * KTOT + 255) / 256, 256>>>(W_in, W_out, b1, b2);

    cudaFuncSetAttribute(dense_block_end,
                         cudaFuncAttributeMaxDynamicSharedMemorySize, SMEM_TOTAL);
    dense_block_end<<<131072 / CTA_M, NTHREADS, SMEM_TOTAL>>>(m_ib, m_bo, m_w, node, msl, out);
}

// round 13
// speedup vs baseline: 1.0873x; 1.0873x over previous
#include <cuda_runtime.h>
#include <cuda.h>
#include <cstdint>

// ============================================================================
// DenseBlockEnd: out = relu(mask * (node + beta1*einsum(ib,W_in) + beta2*einsum(bo,W_out)))
// Fused GEMM M=131072, N=256, K=768 via warp-level mma.sync tf32.
// CTA = 128 rows x 256 cols. 16 compute warps (32x64 each) + 1 TMA producer.
// R12: revert R11 mask-branching (regression). Back to R9 inner loop, plus
// per-warp ks staggering (by warp-row, distinct within each SMSP) so LDSM
// and MMA phases of co-resident warps overlap instead of phase-locking.
// ============================================================================

#define FDIM    256
#define KTOT    768
#define CTA_M   128
#define KC      32
#define NCHUNK  (KTOT / KC)         // 24
#define STAGES  4
#define A_STAGE (CTA_M * KC * 4)    // 16384
#define B_STAGE (FDIM * KC * 4)     // 32768
#define STAGE_BYTES (A_STAGE + B_STAGE)   // 49152
#define SMEM_HDR    1024
#define SMEM_TOTAL  (SMEM_HDR + STAGES * STAGE_BYTES)  // 197632
#define NCWARP      16
#define NTHREADS    (NCWARP * 32 + 32)    // 544

// Weight scratch: Wt[n][k] = beta(seg) * W_seg[k%256][n], tf32-RNA-rounded.
__device__ __align__(1024) float g_Wt[FDIM * KTOT];

// ---------------------------------------------------------------------------
// PTX helpers
// ---------------------------------------------------------------------------
__device__ __forceinline__ uint32_t smem_u32(const void* p) {
    uint32_t a;
    asm("{ .reg .u64 t; cvta.to.shared.u64 t, %1; cvt.u32.u64 %0, t; }" : "=r"(a) : "l"(p));
    return a;
}

#define MBAR_INIT(addr, cnt) \
    asm volatile("mbarrier.init.shared.b64 [%0], %1;" :: "r"(addr), "r"(cnt) : "memory")

#define MBAR_EXPECT(addr, bytes) \
    asm volatile("mbarrier.arrive.expect_tx.shared.b64 _, [%0], %1;" \
                 :: "r"(addr), "r"((uint32_t)(bytes)) : "memory")

#define MBAR_ARRIVE(addr) \
    asm volatile("mbarrier.arrive.shared.b64 _, [%0];" :: "r"(addr) : "memory")

#define MBAR_WAIT(addr, par) do { \
    asm volatile("{\n\t.reg .pred P;\n\tWL_%=:\n\t" \
        "mbarrier.try_wait.parity.acquire.cta.shared::cta.b64 P, [%0], %1, 0x989680;\n\t" \
        "@P bra.uni WD_%=;\n\tbra.uni WL_%=;\n\tWD_%=:\n\t}" \
        :: "r"(addr), "r"((uint32_t)(par)) : "memory"); \
} while (0)

__device__ __forceinline__ void tma2d(uint32_t dst, const void* map, int x, int y, uint32_t mbar) {
    asm volatile(
        "cp.async.bulk.tensor.2d.shared::cta.global.tile.mbarrier::complete_tx::bytes "
        "[%0], [%1, {%2, %3}], [%4];"
        :: "r"(dst), "l"(map), "r"(x), "r"(y), "r"(mbar) : "memory");
}

__device__ __forceinline__ uint32_t swz(uint32_t b) {   // SW128: bits[6:4] ^= bits[9:7]
    return b ^ ((b >> 3) & 0x70);
}

// ldmatrix x4: four 8x8 b16 submatrices (= four 8x4 tf32 tiles).
__device__ __forceinline__ void ldsm_x4(uint32_t* r, uint32_t addr) {
    asm volatile("ldmatrix.sync.aligned.m8n8.x4.shared.b16 {%0,%1,%2,%3}, [%4];"
        : "=r"(r[0]), "=r"(r[1]), "=r"(r[2]), "=r"(r[3]) : "r"(addr));
}

// D += A(16x8, row) * B(8x8, col); tf32 operands in raw b32 regs, fp32 accum.
__device__ __forceinline__ void mma_tf32(float* d, const uint32_t* a, const uint32_t* b) {
    asm volatile(
        "mma.sync.aligned.m16n8k8.row.col.f32.tf32.tf32.f32 "
        "{%0,%1,%2,%3}, {%4,%5,%6,%7}, {%8,%9}, {%0,%1,%2,%3};"
        : "+f"(d[0]), "+f"(d[1]), "+f"(d[2]), "+f"(d[3])
        : "r"(a[0]), "r"(a[1]), "r"(a[2]), "r"(a[3]), "r"(b[0]), "r"(b[1]));
}

// ---------------------------------------------------------------------------
// Prologue: scaled, transposed, tf32-RNA-rounded weights -> g_Wt[n][k]
// ---------------------------------------------------------------------------
__global__ void prep_weights(const float* __restrict__ W_in, const float* __restrict__ W_out,
                             const float* __restrict__ beta1, const float* __restrict__ beta2) {
    int idx = blockIdx.x * blockDim.x + threadIdx.x;
    if (idx >= FDIM * KTOT) return;
    int n = idx / KTOT;
    int k = idx - n * KTOT;
    int seg = k >> 8;           // 0,1 -> W_in layer; 2 -> W_out
    int kk  = k & 255;
    float v;
    if (seg < 2) v = beta1[0] * W_in[seg * 65536 + kk * 256 + n];
    else         v = beta2[0] * W_out[kk * 256 + n];
    uint32_t u;
    asm("cvt.rna.tf32.f32 %0, %1;" : "=r"(u) : "f"(v));
    g_Wt[idx] = __uint_as_float(u);
}

// ---------------------------------------------------------------------------
// Main kernel
// ---------------------------------------------------------------------------
__global__ void __launch_bounds__(NTHREADS, 1) dense_block_end(
    const __grid_constant__ CUtensorMap tma_ib,   // inblock_acts viewed [262144, 256] f32
    const __grid_constant__ CUtensorMap tma_bo,   // block_outputs viewed [131072, 256] f32
    const __grid_constant__ CUtensorMap tma_w,    // g_Wt viewed [256 n, 768 k] f32
    const float* __restrict__ node,
    const int*   __restrict__ mol_slice,
    float*       __restrict__ out)
{
    extern __shared__ char smem[];
    const uint32_t sb  = smem_u32(smem);
    const int tid = threadIdx.x;
    const int wid = tid >> 5;
    const int lid = tid & 31;
    const int bid = blockIdx.x;
    const int R0  = bid * CTA_M;                 // global row base

    const int slice     = mol_slice[bid >> 1];
    const int slice_loc = slice - ((bid & 1) << 7);    // rows valid in this CTA

    // ---- fully-masked CTA: zero-fill 128x256 and exit (no loads, no MMA) ----
    if (slice_loc <= 0) {
        float4* o4 = (float4*)(out + (size_t)R0 * FDIM);
        const float4 z = make_float4(0.f, 0.f, 0.f, 0.f);
        for (int i = tid; i < CTA_M * (FDIM / 4); i += NTHREADS) o4[i] = z;
        return;
    }

    // barriers: full[s] @ sb + 8s (s=0..3), empty[s] @ sb + 32 + 8s
    if (tid == 0) {
        #pragma unroll
        for (int s = 0; s < STAGES; ++s) {
            MBAR_INIT(sb + 8 * s, 1);            // full: 1 expect-tx arrival
            MBAR_INIT(sb + 32 + 8 * s, NCWARP);  // empty: all compute warps
        }
    }
    __syncthreads();

    // ------------------------- producer warp (wid == 16) --------------------
    if (wid == NCWARP) {
        if (lid == 0) {
            #pragma unroll 1
            for (int c = 0; c < NCHUNK; ++c) {
                const int s  = c & 3;
                const int pe = 1 ^ ((c >> 2) & 1);     // flipped phase: first pass free
                MBAR_WAIT(sb + 32 + 8 * s, pe);
                const uint32_t mb = sb + 8 * s;
                MBAR_EXPECT(mb, STAGE_BYTES);
                const int seg = c >> 3;                 // 8 chunks per 256-K segment
                const int k0  = (c & 7) * KC;
                const int y   = (seg == 1) ? 131072 + R0 : R0;
                const void* mp = (seg < 2) ? (const void*)&tma_ib : (const void*)&tma_bo;
                const uint32_t stg = sb + SMEM_HDR + s * STAGE_BYTES;
                tma2d(stg,           mp,     k0,     y, mb);   // A: 128 rows x 32 k
                tma2d(stg + A_STAGE, &tma_w, c * KC, 0, mb);   // B: 256 n   x 32 k
            }
        }
        return;
    }

    // ------------------------- compute warps (wid 0..15) --------------------
    const int wm   = wid >> 2;         // warp row (0..3) -> 32 rows; ALSO ks stagger
    const int wn   = wid & 3;          // warp col (0..3) -> 64 cols
    const int sub  = lid >> 3;         // ldmatrix submatrix id (0..3)
    const int srow = lid & 7;          // row within submatrix

    // ldmatrix lane-address row/k decomposition (see R9):
    const uint32_t aRowL = (uint32_t)(wm * 32 + (sub & 1) * 8 + srow);
    const uint32_t aKoff = (uint32_t)((sub >> 1) * 4);
    const uint32_t bRowL = (uint32_t)(wn * 64 + (sub >> 1) * 8 + srow);
    const uint32_t bKoff = (uint32_t)((sub & 1) * 4);

    // precomputed lane base offsets (k-independent part)
    const uint32_t aOff0 = aRowL * 128 + aKoff * 4;
    const uint32_t bOff0 = bRowL * 128 + bKoff * 4;

    float acc[2][8][4];                // 64 accumulator regs
    #pragma unroll
    for (int i = 0; i < 2; ++i)
        #pragma unroll
        for (int j = 0; j < 8; ++j)
            #pragma unroll
            for (int q = 0; q < 4; ++q) acc[i][j][q] = 0.f;

    #pragma unroll 1
    for (int c = 0; c < NCHUNK; ++c) {
        const int s = c & 3;
        MBAR_WAIT(sb + 8 * s, (c >> 2) & 1);
        const uint32_t aBase = sb + SMEM_HDR + s * STAGE_BYTES;
        const uint32_t bBase = aBase + A_STAGE;

        #pragma unroll
        for (int kk = 0; kk < 4; ++kk) {
            // stagger: warps on the same SMSP (wid = s, s+4, s+8, s+12) have
            // distinct wm -> distinct ks at any instant -> LDSM/MMA overlap
            const uint32_t k0 = (uint32_t)(((kk + wm) & 3) * 32);   // byte offset of ks
            uint32_t af[2][4];
            #pragma unroll
            for (int mt = 0; mt < 2; ++mt)
                ldsm_x4(af[mt], aBase + swz(aOff0 + mt * 2048 + k0));
            uint32_t bf[4][4];
            #pragma unroll
            for (int pr = 0; pr < 4; ++pr)   // pr covers nt pair (2*pr, 2*pr+1)
                ldsm_x4(bf[pr], bBase + swz(bOff0 + pr * 2048 + k0));
            #pragma unroll
            for (int mt = 0; mt < 2; ++mt)
                #pragma unroll
                for (int nt = 0; nt < 8; ++nt)
                    mma_tf32(acc[mt][nt], af[mt], &bf[nt >> 1][(nt & 1) * 2]);
        }
        __syncwarp();
        if (lid == 0) MBAR_ARRIVE(sb + 32 + 8 * s);   // stage reusable
    }

    // ------------------------- fused epilogue -------------------------------
    // D frag: c0:(g,2tig) c1:(g,2tig+1) c2:(g+8,2tig) c3:(g+8,2tig+1)
    const int g   = lid >> 2;
    const int tig = lid & 3;
    #pragma unroll
    for (int mt = 0; mt < 2; ++mt) {
        #pragma unroll
        for (int h = 0; h < 2; ++h) {
            const int rloc = wm * 32 + mt * 16 + g + h * 8;
            float2* orow = (float2*)(out + (size_t)(R0 + rloc) * FDIM);
            if (rloc < slice_loc) {
                const float2* nrow = (const float2*)(node + (size_t)(R0 + rloc) * FDIM);
                #pragma unroll
                for (int nt = 0; nt < 8; ++nt) {
                    const int ci = (wn * 64 + nt * 8 + 2 * tig) >> 1;   // float2 index
                    const float2 nv = nrow[ci];
                    float2 o;
                    o.x = fmaxf(nv.x + acc[mt][nt][h * 2 + 0], 0.f);
                    o.y = fmaxf(nv.y + acc[mt][nt][h * 2 + 1], 0.f);
                    orow[ci] = o;
                }
            } else {
                const float2 z = make_float2(0.f, 0.f);
                #pragma unroll
                for (int nt = 0; nt < 8; ++nt)
                    orow[(wn * 64 + nt * 8 + 2 * tig) >> 1] = z;
            }
        }
    }
}

// ---------------------------------------------------------------------------
// Host launcher
// ---------------------------------------------------------------------------
typedef CUresult (CUDAAPI *PFN_TMAP)(
    CUtensorMap*, CUtensorMapDataType, cuuint32_t, void*,
    const cuuint64_t*, const cuuint64_t*, const cuuint32_t*, const cuuint32_t*,
    CUtensorMapInterleave, CUtensorMapSwizzle, CUtensorMapL2promotion, CUtensorMapFloatOOBfill);

extern "C" void kernel_launch(void* const* d_in, const int* in_sizes, int n_in,
                              void* d_out, int out_size) {
    const float* node  = (const float*)d_in[0];
    const float* ib    = (const float*)d_in[1];
    const float* bo    = (const float*)d_in[2];
    const int*   msl   = (const int*)d_in[3];
    const float* W_in  = (const float*)d_in[4];
    const float* W_out = (const float*)d_in[5];
    const float* b1    = (const float*)d_in[6];
    const float* b2    = (const float*)d_in[7];
    float* out = (float*)d_out;

    static PFN_TMAP pfn = nullptr;
    if (!pfn) {
        void* p = nullptr;
        cudaDriverEntryPointQueryResult qr;
        cudaGetDriverEntryPoint("cuTensorMapEncodeTiled", &p, cudaEnableDefault, &qr);
        pfn = (PFN_TMAP)p;
    }
    void* wptr = nullptr;
    cudaGetSymbolAddress(&wptr, g_Wt);

    CUtensorMap m_ib, m_bo, m_w;
    {   // inblock_acts as [2*131072 rows, 256 floats]; box = 32 x 128
        cuuint64_t dims[2]    = {256, 2ull * 131072};
        cuuint64_t strides[1] = {256 * 4};
        cuuint32_t box[2]     = {KC, CTA_M};
        cuuint32_t es[2]      = {1, 1};
        pfn(&m_ib, CU_TENSOR_MAP_DATA_TYPE_FLOAT32, 2, (void*)ib, dims, strides, box, es,
            CU_TENSOR_MAP_INTERLEAVE_NONE, CU_TENSOR_MAP_SWIZZLE_128B,
            CU_TENSOR_MAP_L2_PROMOTION_L2_128B, CU_TENSOR_MAP_FLOAT_OOB_FILL_NONE);
    }
    {   // block_outputs as [131072 rows, 256 floats]; box = 32 x 128
        cuuint64_t dims[2]    = {256, 131072};
        cuuint64_t strides[1] = {256 * 4};
        cuuint32_t box[2]     = {KC, CTA_M};
        cuuint32_t es[2]      = {1, 1};
        pfn(&m_bo, CU_TENSOR_MAP_DATA_TYPE_FLOAT32, 2, (void*)bo, dims, strides, box, es,
            CU_TENSOR_MAP_INTERLEAVE_NONE, CU_TENSOR_MAP_SWIZZLE_128B,
            CU_TENSOR_MAP_L2_PROMOTION_L2_128B, CU_TENSOR_MAP_FLOAT_OOB_FILL_NONE);
    }
    {   // weights scratch [256 rows(n), 768 floats(k)]; box = 32 x 256
        cuuint64_t dims[2]    = {KTOT, 256};
        cuuint64_t strides[1] = {KTOT * 4};
        cuuint32_t box[2]     = {KC, 256};
        cuuint32_t es[2]      = {1, 1};
        pfn(&m_w, CU_TENSOR_MAP_DATA_TYPE_FLOAT32, 2, wptr, dims, strides, box, es,
            CU_TENSOR_MAP_INTERLEAVE_NONE, CU_TENSOR_MAP_SWIZZLE_128B,
            CU_TENSOR_MAP_L2_PROMOTION_L2_128B, CU_TENSOR_MAP_FLOAT_OOB_FILL_NONE);
    }

    prep_weights<<<(FDIM * KTOT + 255) / 256, 256>>>(W_in, W_out, b1, b2);

    cudaFuncSetAttribute(dense_block_end,
                         cudaFuncAttributeMaxDynamicSharedMemorySize, SMEM_TOTAL);
    dense_block_end<<<131072 / CTA_M, NTHREADS, SMEM_TOTAL>>>(m_ib, m_bo, m_w, node, msl, out);
}

// round 14
// speedup vs baseline: 1.3740x; 1.2637x over previous
#include <cuda_runtime.h>
#include <cuda.h>
#include <cstdint>

// ============================================================================
// DenseBlockEnd: out = relu(mask * (node + beta1*einsum(ib,W_in) + beta2*einsum(bo,W_out)))
// Fused GEMM M=131072, N=256, K=768 via warp-level mma.sync tf32.
// CTA = 128 rows x 256 cols. 16 compute warps (32x64 each) + 1 TMA producer.
// R13: revert R12 stagger (regression). Masked-row skipping via THREE fully
// specialized chunk loops selected once per warp (full / mt0-only / skip),
// each a straight-line R9-shaped body — no conditionals inside the loop.
// ============================================================================

#define FDIM    256
#define KTOT    768
#define CTA_M   128
#define KC      32
#define NCHUNK  (KTOT / KC)         // 24
#define STAGES  4
#define A_STAGE (CTA_M * KC * 4)    // 16384
#define B_STAGE (FDIM * KC * 4)     // 32768
#define STAGE_BYTES (A_STAGE + B_STAGE)   // 49152
#define SMEM_HDR    1024
#define SMEM_TOTAL  (SMEM_HDR + STAGES * STAGE_BYTES)  // 197632
#define NCWARP      16
#define NTHREADS    (NCWARP * 32 + 32)    // 544

// Weight scratch: Wt[n][k] = beta(seg) * W_seg[k%256][n], tf32-RNA-rounded.
__device__ __align__(1024) float g_Wt[FDIM * KTOT];

// ---------------------------------------------------------------------------
// PTX helpers
// ---------------------------------------------------------------------------
__device__ __forceinline__ uint32_t smem_u32(const void* p) {
    uint32_t a;
    asm("{ .reg .u64 t; cvta.to.shared.u64 t, %1; cvt.u32.u64 %0, t; }" : "=r"(a) : "l"(p));
    return a;
}

#define MBAR_INIT(addr, cnt) \
    asm volatile("mbarrier.init.shared.b64 [%0], %1;" :: "r"(addr), "r"(cnt) : "memory")

#define MBAR_EXPECT(addr, bytes) \
    asm volatile("mbarrier.arrive.expect_tx.shared.b64 _, [%0], %1;" \
                 :: "r"(addr), "r"((uint32_t)(bytes)) : "memory")

#define MBAR_ARRIVE(addr) \
    asm volatile("mbarrier.arrive.shared.b64 _, [%0];" :: "r"(addr) : "memory")

#define MBAR_WAIT(addr, par) do { \
    asm volatile("{\n\t.reg .pred P;\n\tWL_%=:\n\t" \
        "mbarrier.try_wait.parity.acquire.cta.shared::cta.b64 P, [%0], %1, 0x989680;\n\t" \
        "@P bra.uni WD_%=;\n\tbra.uni WL_%=;\n\tWD_%=:\n\t}" \
        :: "r"(addr), "r"((uint32_t)(par)) : "memory"); \
} while (0)

__device__ __forceinline__ void tma2d(uint32_t dst, const void* map, int x, int y, uint32_t mbar) {
    asm volatile(
        "cp.async.bulk.tensor.2d.shared::cta.global.tile.mbarrier::complete_tx::bytes "
        "[%0], [%1, {%2, %3}], [%4];"
        :: "r"(dst), "l"(map), "r"(x), "r"(y), "r"(mbar) : "memory");
}

__device__ __forceinline__ uint32_t swz(uint32_t b) {   // SW128: bits[6:4] ^= bits[9:7]
    return b ^ ((b >> 3) & 0x70);
}

// ldmatrix x4: four 8x8 b16 submatrices (= four 8x4 tf32 tiles).
__device__ __forceinline__ void ldsm_x4(uint32_t* r, uint32_t addr) {
    asm volatile("ldmatrix.sync.aligned.m8n8.x4.shared.b16 {%0,%1,%2,%3}, [%4];"
        : "=r"(r[0]), "=r"(r[1]), "=r"(r[2]), "=r"(r[3]) : "r"(addr));
}

// ldmatrix x2: two 8x8 b16 submatrices (for mt0-only A fragments).
__device__ __forceinline__ void ldsm_x2(uint32_t* r, uint32_t addr) {
    asm volatile("ldmatrix.sync.aligned.m8n8.x2.shared.b16 {%0,%1}, [%2];"
        : "=r"(r[0]), "=r"(r[1]) : "r"(addr));
}

// D += A(16x8, row) * B(8x8, col); tf32 operands in raw b32 regs, fp32 accum.
__device__ __forceinline__ void mma_tf32(float* d, const uint32_t* a, const uint32_t* b) {
    asm volatile(
        "mma.sync.aligned.m16n8k8.row.col.f32.tf32.tf32.f32 "
        "{%0,%1,%2,%3}, {%4,%5,%6,%7}, {%8,%9}, {%0,%1,%2,%3};"
        : "+f"(d[0]), "+f"(d[1]), "+f"(d[2]), "+f"(d[3])
        : "r"(a[0]), "r"(a[1]), "r"(a[2]), "r"(a[3]), "r"(b[0]), "r"(b[1]));
}

// ---------------------------------------------------------------------------
// Prologue: scaled, transposed, tf32-RNA-rounded weights -> g_Wt[n][k]
// ---------------------------------------------------------------------------
__global__ void prep_weights(const float* __restrict__ W_in, const float* __restrict__ W_out,
                             const float* __restrict__ beta1, const float* __restrict__ beta2) {
    int idx = blockIdx.x * blockDim.x + threadIdx.x;
    if (idx >= FDIM * KTOT) return;
    int n = idx / KTOT;
    int k = idx - n * KTOT;
    int seg = k >> 8;           // 0,1 -> W_in layer; 2 -> W_out
    int kk  = k & 255;
    float v;
    if (seg < 2) v = beta1[0] * W_in[seg * 65536 + kk * 256 + n];
    else         v = beta2[0] * W_out[kk * 256 + n];
    uint32_t u;
    asm("cvt.rna.tf32.f32 %0, %1;" : "=r"(u) : "f"(v));
    g_Wt[idx] = __uint_as_float(u);
}

// ---------------------------------------------------------------------------
// Main kernel
// ---------------------------------------------------------------------------
__global__ void __launch_bounds__(NTHREADS, 1) dense_block_end(
    const __grid_constant__ CUtensorMap tma_ib,   // inblock_acts viewed [262144, 256] f32
    const __grid_constant__ CUtensorMap tma_bo,   // block_outputs viewed [131072, 256] f32
    const __grid_constant__ CUtensorMap tma_w,    // g_Wt viewed [256 n, 768 k] f32
    const float* __restrict__ node,
    const int*   __restrict__ mol_slice,
    float*       __restrict__ out)
{
    extern __shared__ char smem[];
    const uint32_t sb  = smem_u32(smem);
    const int tid = threadIdx.x;
    const int wid = tid >> 5;
    const int lid = tid & 31;
    const int bid = blockIdx.x;
    const int R0  = bid * CTA_M;                 // global row base

    const int slice     = mol_slice[bid >> 1];
    const int slice_loc = slice - ((bid & 1) << 7);    // rows valid in this CTA

    // ---- fully-masked CTA: zero-fill 128x256 and exit (no loads, no MMA) ----
    if (slice_loc <= 0) {
        float4* o4 = (float4*)(out + (size_t)R0 * FDIM);
        const float4 z = make_float4(0.f, 0.f, 0.f, 0.f);
        for (int i = tid; i < CTA_M * (FDIM / 4); i += NTHREADS) o4[i] = z;
        return;
    }

    // barriers: full[s] @ sb + 8s (s=0..3), empty[s] @ sb + 32 + 8s
    if (tid == 0) {
        #pragma unroll
        for (int s = 0; s < STAGES; ++s) {
            MBAR_INIT(sb + 8 * s, 1);            // full: 1 expect-tx arrival
            MBAR_INIT(sb + 32 + 8 * s, NCWARP);  // empty: all compute warps
        }
    }
    __syncthreads();

    // ------------------------- producer warp (wid == 16) --------------------
    if (wid == NCWARP) {
        if (lid == 0) {
            #pragma unroll 1
            for (int c = 0; c < NCHUNK; ++c) {
                const int s  = c & 3;
                const int pe = 1 ^ ((c >> 2) & 1);     // flipped phase: first pass free
                MBAR_WAIT(sb + 32 + 8 * s, pe);
                const uint32_t mb = sb + 8 * s;
                MBAR_EXPECT(mb, STAGE_BYTES);
                const int seg = c >> 3;                 // 8 chunks per 256-K segment
                const int k0  = (c & 7) * KC;
                const int y   = (seg == 1) ? 131072 + R0 : R0;
                const void* mp = (seg < 2) ? (const void*)&tma_ib : (const void*)&tma_bo;
                const uint32_t stg = sb + SMEM_HDR + s * STAGE_BYTES;
                tma2d(stg,           mp,     k0,     y, mb);   // A: 128 rows x 32 k
                tma2d(stg + A_STAGE, &tma_w, c * KC, 0, mb);   // B: 256 n   x 32 k
            }
        }
        return;
    }

    // ------------------------- compute warps (wid 0..15) --------------------
    const int wm   = wid >> 2;         // warp row (0..3) -> 32 rows
    const int wn   = wid & 3;          // warp col (0..3) -> 64 cols
    const int sub  = lid >> 3;         // ldmatrix submatrix id (0..3)
    const int srow = lid & 7;          // row within submatrix

    // ldmatrix lane-address row/k decomposition (see R9):
    const uint32_t aRowL = (uint32_t)(wm * 32 + (sub & 1) * 8 + srow);
    const uint32_t aKoff = (uint32_t)((sub >> 1) * 4);
    const uint32_t bRowL = (uint32_t)(wn * 64 + (sub >> 1) * 8 + srow);
    const uint32_t bKoff = (uint32_t)((sub & 1) * 4);
    // x2 variant lane mapping for A mt0-only: subs 0,1 used (lanes 0-15 addr)
    const uint32_t aRowX2 = (uint32_t)(wm * 32 + ((lid >> 3) & 1) * 8 + srow);
    const uint32_t aKX2   = (uint32_t)(((lid >> 4) & 1) * 4);   // lanes 16+ ignored by x2? keep x4-compatible
    (void)aRowX2; (void)aKX2;

    const int warp_rows = slice_loc - wm * 32;   // live rows for this warp

    float acc[2][8][4];                // 64 accumulator regs
    #pragma unroll
    for (int i = 0; i < 2; ++i)
        #pragma unroll
        for (int j = 0; j < 8; ++j)
            #pragma unroll
            for (int q = 0; q < 4; ++q) acc[i][j][q] = 0.f;

    if (warp_rows > 16) {
        // ---------------- FULL loop: both 16-row halves live (R9 verbatim) ---
        #pragma unroll 1
        for (int c = 0; c < NCHUNK; ++c) {
            const int s = c & 3;
            MBAR_WAIT(sb + 8 * s, (c >> 2) & 1);
            const uint32_t aBase = sb + SMEM_HDR + s * STAGE_BYTES;
            const uint32_t bBase = aBase + A_STAGE;
            #pragma unroll
            for (int ks = 0; ks < 4; ++ks) {
                const uint32_t k0 = ks * 8;
                uint32_t af[2][4];
                #pragma unroll
                for (int mt = 0; mt < 2; ++mt)
                    ldsm_x4(af[mt], aBase + swz((aRowL + mt * 16) * 128 + (k0 + aKoff) * 4));
                uint32_t bf[4][4];
                #pragma unroll
                for (int pr = 0; pr < 4; ++pr)
                    ldsm_x4(bf[pr], bBase + swz((bRowL + pr * 16) * 128 + (k0 + bKoff) * 4));
                #pragma unroll
                for (int mt = 0; mt < 2; ++mt)
                    #pragma unroll
                    for (int nt = 0; nt < 8; ++nt)
                        mma_tf32(acc[mt][nt], af[mt], &bf[nt >> 1][(nt & 1) * 2]);
            }
            __syncwarp();
            if (lid == 0) MBAR_ARRIVE(sb + 32 + 8 * s);
        }
    } else if (warp_rows > 0) {
        // ---------------- HALF loop: only rows wm*32..wm*32+15 live ----------
        #pragma unroll 1
        for (int c = 0; c < NCHUNK; ++c) {
            const int s = c & 3;
            MBAR_WAIT(sb + 8 * s, (c >> 2) & 1);
            const uint32_t aBase = sb + SMEM_HDR + s * STAGE_BYTES;
            const uint32_t bBase = aBase + A_STAGE;
            #pragma unroll
            for (int ks = 0; ks < 4; ++ks) {
                const uint32_t k0 = ks * 8;
                uint32_t af0[4];
                ldsm_x4(af0, aBase + swz(aRowL * 128 + (k0 + aKoff) * 4));
                uint32_t bf[4][4];
                #pragma unroll
                for (int pr = 0; pr < 4; ++pr)
                    ldsm_x4(bf[pr], bBase + swz((bRowL + pr * 16) * 128 + (k0 + bKoff) * 4));
                #pragma unroll
                for (int nt = 0; nt < 8; ++nt)
                    mma_tf32(acc[0][nt], af0, &bf[nt >> 1][(nt & 1) * 2]);
            }
            __syncwarp();
            if (lid == 0) MBAR_ARRIVE(sb + 32 + 8 * s);
        }
    } else {
        // ---------------- SKIP loop: barrier protocol only -------------------
        #pragma unroll 1
        for (int c = 0; c < NCHUNK; ++c) {
            const int s = c & 3;
            MBAR_WAIT(sb + 8 * s, (c >> 2) & 1);
            __syncwarp();
            if (lid == 0) MBAR_ARRIVE(sb + 32 + 8 * s);
        }
    }

    // ------------------------- fused epilogue -------------------------------
    // D frag: c0:(g,2tig) c1:(g,2tig+1) c2:(g+8,2tig) c3:(g+8,2tig+1)
    const int g   = lid >> 2;
    const int tig = lid & 3;
    #pragma unroll
    for (int mt = 0; mt < 2; ++mt) {
        #pragma unroll
        for (int h = 0; h < 2; ++h) {
            const int rloc = wm * 32 + mt * 16 + g + h * 8;
            float2* orow = (float2*)(out + (size_t)(R0 + rloc) * FDIM);
            if (rloc < slice_loc) {
                const float2* nrow = (const float2*)(node + (size_t)(R0 + rloc) * FDIM);
                #pragma unroll
                for (int nt = 0; nt < 8; ++nt) {
                    const int ci = (wn * 64 + nt * 8 + 2 * tig) >> 1;   // float2 index
                    const float2 nv = nrow[ci];
                    float2 o;
                    o.x = fmaxf(nv.x + acc[mt][nt][h * 2 + 0], 0.f);
                    o.y = fmaxf(nv.y + acc[mt][nt][h * 2 + 1], 0.f);
                    orow[ci] = o;
                }
            } else {
                const float2 z = make_float2(0.f, 0.f);
                #pragma unroll
                for (int nt = 0; nt < 8; ++nt)
                    orow[(wn * 64 + nt * 8 + 2 * tig) >> 1] = z;
            }
        }
    }
}

// ---------------------------------------------------------------------------
// Host launcher
// ---------------------------------------------------------------------------
typedef CUresult (CUDAAPI *PFN_TMAP)(
    CUtensorMap*, CUtensorMapDataType, cuuint32_t, void*,
    const cuuint64_t*, const cuuint64_t*, const cuuint32_t*, const cuuint32_t*,
    CUtensorMapInterleave, CUtensorMapSwizzle, CUtensorMapL2promotion, CUtensorMapFloatOOBfill);

extern "C" void kernel_launch(void* const* d_in, const int* in_sizes, int n_in,
                              void* d_out, int out_size) {
    const float* node  = (const float*)d_in[0];
    const float* ib    = (const float*)d_in[1];
    const float* bo    = (const float*)d_in[2];
    const int*   msl   = (const int*)d_in[3];
    const float* W_in  = (const float*)d_in[4];
    const float* W_out = (const float*)d_in[5];
    const float* b1    = (const float*)d_in[6];
    const float* b2    = (const float*)d_in[7];
    float* out = (float*)d_out;

    static PFN_TMAP pfn = nullptr;
    if (!pfn) {
        void* p = nullptr;
        cudaDriverEntryPointQueryResult qr;
        cudaGetDriverEntryPoint("cuTensorMapEncodeTiled", &p, cudaEnableDefault, &qr);
        pfn = (PFN_TMAP)p;
    }
    void* wptr = nullptr;
    cudaGetSymbolAddress(&wptr, g_Wt);

    CUtensorMap m_ib, m_bo, m_w;
    {   // inblock_acts as [2*131072 rows, 256 floats]; box = 32 x 128
        cuuint64_t dims[2]    = {256, 2ull * 131072};
        cuuint64_t strides[1] = {256 * 4};
        cuuint32_t box[2]     = {KC, CTA_M};
        cuuint32_t es[2]      = {1, 1};
        pfn(&m_ib, CU_TENSOR_MAP_DATA_TYPE_FLOAT32, 2, (void*)ib, dims, strides, box, es,
            CU_TENSOR_MAP_INTERLEAVE_NONE, CU_TENSOR_MAP_SWIZZLE_128B,
            CU_TENSOR_MAP_L2_PROMOTION_L2_128B, CU_TENSOR_MAP_FLOAT_OOB_FILL_NONE);
    }
    {   // block_outputs as [131072 rows, 256 floats]; box = 32 x 128
        cuuint64_t dims[2]    = {256, 131072};
        cuuint64_t strides[1] = {256 * 4};
        cuuint32_t box[2]     = {KC, CTA_M};
        cuuint32_t es[2]      = {1, 1};
        pfn(&m_bo, CU_TENSOR_MAP_DATA_TYPE_FLOAT32, 2, (void*)bo, dims, strides, box, es,
            CU_TENSOR_MAP_INTERLEAVE_NONE, CU_TENSOR_MAP_SWIZZLE_128B,
            CU_TENSOR_MAP_L2_PROMOTION_L2_128B, CU_TENSOR_MAP_FLOAT_OOB_FILL_NONE);
    }
    {   // weights scratch [256 rows(n), 768 floats(k)]; box = 32 x 256
        cuuint64_t dims[2]    = {KTOT, 256};
        cuuint64_t strides[1] = {KTOT * 4};
        cuuint32_t box[2]     = {KC, 256};
        cuuint32_t es[2]      = {1, 1};
        pfn(&m_w, CU_TENSOR_MAP_DATA_TYPE_FLOAT32, 2, wptr, dims, strides, box, es,
            CU_TENSOR_MAP_INTERLEAVE_NONE, CU_TENSOR_MAP_SWIZZLE_128B,
            CU_TENSOR_MAP_L2_PROMOTION_L2_128B, CU_TENSOR_MAP_FLOAT_OOB_FILL_NONE);
    }

    prep_weights<<<(FDIM * KTOT + 255) / 256, 256>>>(W_in, W_out, b1, b2);

    cudaFuncSetAttribute(dense_block_end,
                         cudaFuncAttributeMaxDynamicSharedMemorySize, SMEM_TOTAL);
    dense_block_end<<<131072 / CTA_M, NTHREADS, SMEM_TOTAL>>>(m_ib, m_bo, m_w, node, msl, out);
}

// round 15
// speedup vs baseline: 1.5745x; 1.1460x over previous
#include <cuda_runtime.h>
#include <cuda.h>
#include <cstdint>

// ============================================================================
// DenseBlockEnd: out = relu(mask * (node + beta1*einsum(ib,W_in) + beta2*einsum(bo,W_out)))
// Fused GEMM M=131072, N=256, K=768 via warp-level mma.sync tf32.
// R14: CTA halved to 64 rows (8 compute warps + 1 producer, STAGES=2) so TWO
// CTAs co-reside per SM (occ 23.7% -> ~45%). Inner loop bodies identical to
// R13 (full / half / skip specialized straight-line loops).
// ============================================================================

#define FDIM    256
#define KTOT    768
#define CTA_M   64
#define KC      32
#define NCHUNK  (KTOT / KC)         // 24
#define STAGES  2
#define A_STAGE (CTA_M * KC * 4)    // 8192
#define B_STAGE (FDIM * KC * 4)     // 32768
#define STAGE_BYTES (A_STAGE + B_STAGE)   // 40960
#define SMEM_HDR    1024
#define SMEM_TOTAL  (SMEM_HDR + STAGES * STAGE_BYTES)  // 82944  (x2 CTAs = 165888)
#define NCWARP      8
#define NTHREADS    (NCWARP * 32 + 32)    // 288

// Weight scratch: Wt[n][k] = beta(seg) * W_seg[k%256][n], tf32-RNA-rounded.
__device__ __align__(1024) float g_Wt[FDIM * KTOT];

// ---------------------------------------------------------------------------
// PTX helpers
// ---------------------------------------------------------------------------
__device__ __forceinline__ uint32_t smem_u32(const void* p) {
    uint32_t a;
    asm("{ .reg .u64 t; cvta.to.shared.u64 t, %1; cvt.u32.u64 %0, t; }" : "=r"(a) : "l"(p));
    return a;
}

#define MBAR_INIT(addr, cnt) \
    asm volatile("mbarrier.init.shared.b64 [%0], %1;" :: "r"(addr), "r"(cnt) : "memory")

#define MBAR_EXPECT(addr, bytes) \
    asm volatile("mbarrier.arrive.expect_tx.shared.b64 _, [%0], %1;" \
                 :: "r"(addr), "r"((uint32_t)(bytes)) : "memory")

#define MBAR_ARRIVE(addr) \
    asm volatile("mbarrier.arrive.shared.b64 _, [%0];" :: "r"(addr) : "memory")

#define MBAR_WAIT(addr, par) do { \
    asm volatile("{\n\t.reg .pred P;\n\tWL_%=:\n\t" \
        "mbarrier.try_wait.parity.acquire.cta.shared::cta.b64 P, [%0], %1, 0x989680;\n\t" \
        "@P bra.uni WD_%=;\n\tbra.uni WL_%=;\n\tWD_%=:\n\t}" \
        :: "r"(addr), "r"((uint32_t)(par)) : "memory"); \
} while (0)

__device__ __forceinline__ void tma2d(uint32_t dst, const void* map, int x, int y, uint32_t mbar) {
    asm volatile(
        "cp.async.bulk.tensor.2d.shared::cta.global.tile.mbarrier::complete_tx::bytes "
        "[%0], [%1, {%2, %3}], [%4];"
        :: "r"(dst), "l"(map), "r"(x), "r"(y), "r"(mbar) : "memory");
}

__device__ __forceinline__ uint32_t swz(uint32_t b) {   // SW128: bits[6:4] ^= bits[9:7]
    return b ^ ((b >> 3) & 0x70);
}

// ldmatrix x4: four 8x8 b16 submatrices (= four 8x4 tf32 tiles).
__device__ __forceinline__ void ldsm_x4(uint32_t* r, uint32_t addr) {
    asm volatile("ldmatrix.sync.aligned.m8n8.x4.shared.b16 {%0,%1,%2,%3}, [%4];"
        : "=r"(r[0]), "=r"(r[1]), "=r"(r[2]), "=r"(r[3]) : "r"(addr));
}

// D += A(16x8, row) * B(8x8, col); tf32 operands in raw b32 regs, fp32 accum.
__device__ __forceinline__ void mma_tf32(float* d, const uint32_t* a, const uint32_t* b) {
    asm volatile(
        "mma.sync.aligned.m16n8k8.row.col.f32.tf32.tf32.f32 "
        "{%0,%1,%2,%3}, {%4,%5,%6,%7}, {%8,%9}, {%0,%1,%2,%3};"
        : "+f"(d[0]), "+f"(d[1]), "+f"(d[2]), "+f"(d[3])
        : "r"(a[0]), "r"(a[1]), "r"(a[2]), "r"(a[3]), "r"(b[0]), "r"(b[1]));
}

// ---------------------------------------------------------------------------
// Prologue: scaled, transposed, tf32-RNA-rounded weights -> g_Wt[n][k]
// ---------------------------------------------------------------------------
__global__ void prep_weights(const float* __restrict__ W_in, const float* __restrict__ W_out,
                             const float* __restrict__ beta1, const float* __restrict__ beta2) {
    int idx = blockIdx.x * blockDim.x + threadIdx.x;
    if (idx >= FDIM * KTOT) return;
    int n = idx / KTOT;
    int k = idx - n * KTOT;
    int seg = k >> 8;           // 0,1 -> W_in layer; 2 -> W_out
    int kk  = k & 255;
    float v;
    if (seg < 2) v = beta1[0] * W_in[seg * 65536 + kk * 256 + n];
    else         v = beta2[0] * W_out[kk * 256 + n];
    uint32_t u;
    asm("cvt.rna.tf32.f32 %0, %1;" : "=r"(u) : "f"(v));
    g_Wt[idx] = __uint_as_float(u);
}

// ---------------------------------------------------------------------------
// Main kernel: one CTA = one 64-row quarter of a molecule
// ---------------------------------------------------------------------------
__global__ void __launch_bounds__(NTHREADS, 2) dense_block_end(
    const __grid_constant__ CUtensorMap tma_ib,   // inblock_acts viewed [262144, 256] f32
    const __grid_constant__ CUtensorMap tma_bo,   // block_outputs viewed [131072, 256] f32
    const __grid_constant__ CUtensorMap tma_w,    // g_Wt viewed [256 n, 768 k] f32
    const float* __restrict__ node,
    const int*   __restrict__ mol_slice,
    float*       __restrict__ out)
{
    extern __shared__ char smem[];
    const uint32_t sb  = smem_u32(smem);
    const int tid = threadIdx.x;
    const int wid = tid >> 5;
    const int lid = tid & 31;
    const int bid = blockIdx.x;
    const int R0  = bid * CTA_M;                 // global row base

    const int slice     = mol_slice[bid >> 2];
    const int slice_loc = slice - ((bid & 3) << 6);    // rows valid in this CTA

    // ---- fully-masked CTA: zero-fill 64x256 and exit (no loads, no MMA) ----
    if (slice_loc <= 0) {
        float4* o4 = (float4*)(out + (size_t)R0 * FDIM);
        const float4 z = make_float4(0.f, 0.f, 0.f, 0.f);
        for (int i = tid; i < CTA_M * (FDIM / 4); i += NTHREADS) o4[i] = z;
        return;
    }

    // barriers: full[s] @ sb + 8s (s=0..1), empty[s] @ sb + 32 + 8s
    if (tid == 0) {
        #pragma unroll
        for (int s = 0; s < STAGES; ++s) {
            MBAR_INIT(sb + 8 * s, 1);            // full: 1 expect-tx arrival
            MBAR_INIT(sb + 32 + 8 * s, NCWARP);  // empty: all compute warps
        }
    }
    __syncthreads();

    // ------------------------- producer warp (wid == 8) ---------------------
    if (wid == NCWARP) {
        if (lid == 0) {
            #pragma unroll 1
            for (int c = 0; c < NCHUNK; ++c) {
                const int s  = c & 1;
                const int pe = 1 ^ ((c >> 1) & 1);     // flipped phase: first pass free
                MBAR_WAIT(sb + 32 + 8 * s, pe);
                const uint32_t mb = sb + 8 * s;
                MBAR_EXPECT(mb, STAGE_BYTES);
                const int seg = c >> 3;                 // 8 chunks per 256-K segment
                const int k0  = (c & 7) * KC;
                const int y   = (seg == 1) ? 131072 + R0 : R0;
                const void* mp = (seg < 2) ? (const void*)&tma_ib : (const void*)&tma_bo;
                const uint32_t stg = sb + SMEM_HDR + s * STAGE_BYTES;
                tma2d(stg,           mp,     k0,     y, mb);   // A: 64 rows x 32 k
                tma2d(stg + A_STAGE, &tma_w, c * KC, 0, mb);   // B: 256 n   x 32 k
            }
        }
        return;
    }

    // ------------------------- compute warps (wid 0..7) ---------------------
    const int wm   = wid >> 2;         // warp row (0..1) -> 32 rows
    const int wn   = wid & 3;          // warp col (0..3) -> 64 cols
    const int sub  = lid >> 3;         // ldmatrix submatrix id (0..3)
    const int srow = lid & 7;          // row within submatrix

    // ldmatrix lane-address row/k decomposition (see R9):
    const uint32_t aRowL = (uint32_t)(wm * 32 + (sub & 1) * 8 + srow);
    const uint32_t aKoff = (uint32_t)((sub >> 1) * 4);
    const uint32_t bRowL = (uint32_t)(wn * 64 + (sub >> 1) * 8 + srow);
    const uint32_t bKoff = (uint32_t)((sub & 1) * 4);

    const int warp_rows = slice_loc - wm * 32;   // live rows for this warp

    float acc[2][8][4];                // 64 accumulator regs
    #pragma unroll
    for (int i = 0; i < 2; ++i)
        #pragma unroll
        for (int j = 0; j < 8; ++j)
            #pragma unroll
            for (int q = 0; q < 4; ++q) acc[i][j][q] = 0.f;

    if (warp_rows > 16) {
        // ---------------- FULL loop: both 16-row halves live -----------------
        #pragma unroll 1
        for (int c = 0; c < NCHUNK; ++c) {
            const int s = c & 1;
            MBAR_WAIT(sb + 8 * s, (c >> 1) & 1);
            const uint32_t aBase = sb + SMEM_HDR + s * STAGE_BYTES;
            const uint32_t bBase = aBase + A_STAGE;
            #pragma unroll
            for (int ks = 0; ks < 4; ++ks) {
                const uint32_t k0 = ks * 8;
                uint32_t af[2][4];
                #pragma unroll
                for (int mt = 0; mt < 2; ++mt)
                    ldsm_x4(af[mt], aBase + swz((aRowL + mt * 16) * 128 + (k0 + aKoff) * 4));
                uint32_t bf[4][4];
                #pragma unroll
                for (int pr = 0; pr < 4; ++pr)
                    ldsm_x4(bf[pr], bBase + swz((bRowL + pr * 16) * 128 + (k0 + bKoff) * 4));
                #pragma unroll
                for (int mt = 0; mt < 2; ++mt)
                    #pragma unroll
                    for (int nt = 0; nt < 8; ++nt)
                        mma_tf32(acc[mt][nt], af[mt], &bf[nt >> 1][(nt & 1) * 2]);
            }
            __syncwarp();
            if (lid == 0) MBAR_ARRIVE(sb + 32 + 8 * s);
        }
    } else if (warp_rows > 0) {
        // ---------------- HALF loop: only rows wm*32..wm*32+15 live ----------
        #pragma unroll 1
        for (int c = 0; c < NCHUNK; ++c) {
            const int s = c & 1;
            MBAR_WAIT(sb + 8 * s, (c >> 1) & 1);
            const uint32_t aBase = sb + SMEM_HDR + s * STAGE_BYTES;
            const uint32_t bBase = aBase + A_STAGE;
            #pragma unroll
            for (int ks = 0; ks < 4; ++ks) {
                const uint32_t k0 = ks * 8;
                uint32_t af0[4];
                ldsm_x4(af0, aBase + swz(aRowL * 128 + (k0 + aKoff) * 4));
                uint32_t bf[4][4];
                #pragma unroll
                for (int pr = 0; pr < 4; ++pr)
                    ldsm_x4(bf[pr], bBase + swz((bRowL + pr * 16) * 128 + (k0 + bKoff) * 4));
                #pragma unroll
                for (int nt = 0; nt < 8; ++nt)
                    mma_tf32(acc[0][nt], af0, &bf[nt >> 1][(nt & 1) * 2]);
            }
            __syncwarp();
            if (lid == 0) MBAR_ARRIVE(sb + 32 + 8 * s);
        }
    } else {
        // ---------------- SKIP loop: barrier protocol only -------------------
        #pragma unroll 1
        for (int c = 0; c < NCHUNK; ++c) {
            const int s = c & 1;
            MBAR_WAIT(sb + 8 * s, (c >> 1) & 1);
            __syncwarp();
            if (lid == 0) MBAR_ARRIVE(sb + 32 + 8 * s);
        }
    }

    // ------------------------- fused epilogue -------------------------------
    // D frag: c0:(g,2tig) c1:(g,2tig+1) c2:(g+8,2tig) c3:(g+8,2tig+1)
    const int g   = lid >> 2;
    const int tig = lid & 3;
    #pragma unroll
    for (int mt = 0; mt < 2; ++mt) {
        #pragma unroll
        for (int h = 0; h < 2; ++h) {
            const int rloc = wm * 32 + mt * 16 + g + h * 8;
            float2* orow = (float2*)(out + (size_t)(R0 + rloc) * FDIM);
            if (rloc < slice_loc) {
                const float2* nrow = (const float2*)(node + (size_t)(R0 + rloc) * FDIM);
                #pragma unroll
                for (int nt = 0; nt < 8; ++nt) {
                    const int ci = (wn * 64 + nt * 8 + 2 * tig) >> 1;   // float2 index
                    const float2 nv = nrow[ci];
                    float2 o;
                    o.x = fmaxf(nv.x + acc[mt][nt][h * 2 + 0], 0.f);
                    o.y = fmaxf(nv.y + acc[mt][nt][h * 2 + 1], 0.f);
                    orow[ci] = o;
                }
            } else {
                const float2 z = make_float2(0.f, 0.f);
                #pragma unroll
                for (int nt = 0; nt < 8; ++nt)
                    orow[(wn * 64 + nt * 8 + 2 * tig) >> 1] = z;
            }
        }
    }
}

// ---------------------------------------------------------------------------
// Host launcher
// ---------------------------------------------------------------------------
typedef CUresult (CUDAAPI *PFN_TMAP)(
    CUtensorMap*, CUtensorMapDataType, cuuint32_t, void*,
    const cuuint64_t*, const cuuint64_t*, const cuuint32_t*, const cuuint32_t*,
    CUtensorMapInterleave, CUtensorMapSwizzle, CUtensorMapL2promotion, CUtensorMapFloatOOBfill);

extern "C" void kernel_launch(void* const* d_in, const int* in_sizes, int n_in,
                              void* d_out, int out_size) {
    const float* node  = (const float*)d_in[0];
    const float* ib    = (const float*)d_in[1];
    const float* bo    = (const float*)d_in[2];
    const int*   msl   = (const int*)d_in[3];
    const float* W_in  = (const float*)d_in[4];
    const float* W_out = (const float*)d_in[5];
    const float* b1    = (const float*)d_in[6];
    const float* b2    = (const float*)d_in[7];
    float* out = (float*)d_out;

    static PFN_TMAP pfn = nullptr;
    if (!pfn) {
        void* p = nullptr;
        cudaDriverEntryPointQueryResult qr;
        cudaGetDriverEntryPoint("cuTensorMapEncodeTiled", &p, cudaEnableDefault, &qr);
        pfn = (PFN_TMAP)p;
    }
    void* wptr = nullptr;
    cudaGetSymbolAddress(&wptr, g_Wt);

    CUtensorMap m_ib, m_bo, m_w;
    {   // inblock_acts as [2*131072 rows, 256 floats]; box = 32 x 64
        cuuint64_t dims[2]    = {256, 2ull * 131072};
        cuuint64_t strides[1] = {256 * 4};
        cuuint32_t box[2]     = {KC, CTA_M};
        cuuint32_t es[2]      = {1, 1};
        pfn(&m_ib, CU_TENSOR_MAP_DATA_TYPE_FLOAT32, 2, (void*)ib, dims, strides, box, es,
            CU_TENSOR_MAP_INTERLEAVE_NONE, CU_TENSOR_MAP_SWIZZLE_128B,
            CU_TENSOR_MAP_L2_PROMOTION_L2_128B, CU_TENSOR_MAP_FLOAT_OOB_FILL_NONE);
    }
    {   // block_outputs as [131072 rows, 256 floats]; box = 32 x 64
        cuuint64_t dims[2]    = {256, 131072};
        cuuint64_t strides[1] = {256 * 4};
        cuuint32_t box[2]     = {KC, CTA_M};
        cuuint32_t es[2]      = {1, 1};
        pfn(&m_bo, CU_TENSOR_MAP_DATA_TYPE_FLOAT32, 2, (void*)bo, dims, strides, box, es,
            CU_TENSOR_MAP_INTERLEAVE_NONE, CU_TENSOR_MAP_SWIZZLE_128B,
            CU_TENSOR_MAP_L2_PROMOTION_L2_128B, CU_TENSOR_MAP_FLOAT_OOB_FILL_NONE);
    }
    {   // weights scratch [256 rows(n), 768 floats(k)]; box = 32 x 256
        cuuint64_t dims[2]    = {KTOT, 256};
        cuuint64_t strides[1] = {KTOT * 4};
        cuuint32_t box[2]     = {KC, 256};
        cuuint32_t es[2]      = {1, 1};
        pfn(&m_w, CU_TENSOR_MAP_DATA_TYPE_FLOAT32, 2, wptr, dims, strides, box, es,
            CU_TENSOR_MAP_INTERLEAVE_NONE, CU_TENSOR_MAP_SWIZZLE_128B,
            CU_TENSOR_MAP_L2_PROMOTION_L2_128B, CU_TENSOR_MAP_FLOAT_OOB_FILL_NONE);
    }

    prep_weights<<<(FDIM * KTOT + 255) / 256, 256>>>(W_in, W_out, b1, b2);

    cudaFuncSetAttribute(dense_block_end,
                         cudaFuncAttributeMaxDynamicSharedMemorySize, SMEM_TOTAL);
    dense_block_end<<<131072 / CTA_M, NTHREADS, SMEM_TOTAL>>>(m_ib, m_bo, m_w, node, msl, out);
}